// round 1
// baseline (speedup 1.0000x reference)
#include <cuda_runtime.h>
#include <math.h>

#define BB 16
#define NNODE 512
#define EE 8192
#define CC 128
#define OHH 512
#define ROWS (BB*NNODE)   // 8192

// ---------------- device scratch (static, no allocation) ----------------
__device__ int   g_cnt[ROWS];
__device__ int   g_off[ROWS];
__device__ int   g_cur[ROWS];
__device__ int   g_elist[BB*EE];
__device__ float g_xcat[(size_t)ROWS*136];
__device__ float g_h1[(size_t)ROWS*128];
__device__ float g_sum[128];
__device__ float g_sq[128];
__device__ float g_a[128];
__device__ float g_c[128];

// ---------------- tiny setup kernels ----------------
__global__ void k_zero() {
    int i = blockIdx.x * 256 + threadIdx.x;
    if (i < ROWS) { g_cnt[i] = 0; g_cur[i] = 0; }
    if (i < 128)  { g_sum[i] = 0.f; g_sq[i] = 0.f; }
}

__global__ void k_count(const int* __restrict__ adjs) {
    int i = blockIdx.x * 256 + threadIdx.x;      // 0 .. B*E-1
    int b = i >> 13;                              // E = 8192 = 2^13
    int e = i & (EE - 1);
    int r = adjs[b * 2 * EE + EE + e];
    atomicAdd(&g_cnt[b * NNODE + r], 1);
}

__global__ void k_scan() {  // exclusive prefix per batch, 512 threads
    int b = blockIdx.x, t = threadIdx.x;
    __shared__ int s[NNODE];
    int v0 = g_cnt[b * NNODE + t];
    s[t] = v0;
    __syncthreads();
    for (int off = 1; off < NNODE; off <<= 1) {
        int v = (t >= off) ? s[t - off] : 0;
        __syncthreads();
        s[t] += v;
        __syncthreads();
    }
    g_off[b * NNODE + t] = s[t] - v0;
}

__global__ void k_fill(const int* __restrict__ adjs) {
    int i = blockIdx.x * 256 + threadIdx.x;
    int b = i >> 13;
    int e = i & (EE - 1);
    int snd = adjs[b * 2 * EE + e];
    int r   = adjs[b * 2 * EE + EE + e];
    int pos = atomicAdd(&g_cur[b * NNODE + r], 1);
    g_elist[b * EE + g_off[b * NNODE + r] + pos] = snd;
}

// ---------------- fused per-node kernel ----------------
// gather -> new_oh out -> bitonic sort -> symlog -> conv1 -> conv2 -> mean -> lin -> xcat
__global__ void __launch_bounds__(512) k_fused(
    const float* __restrict__ xs, const float* __restrict__ oh,
    const float* __restrict__ c1w_g, const float* __restrict__ c1b_g,
    const float* __restrict__ c2w_g, const float* __restrict__ c2b_g,
    const float* __restrict__ lw_g,  const float* __restrict__ lb_g,
    float* __restrict__ newoh)
{
    __shared__ float soh[OHH];
    __shared__ float sx[CC];
    __shared__ float hbuf[8][OHH + 2];
    __shared__ float wall[568];          // c1w 24 | c1b 8 | c2w 384 | c2b 16 | lw 128 | lb 8
    __shared__ float red[16 * 16];
    __shared__ float meansh[16], pohsh[8];

    int tid = threadIdx.x;
    int b = blockIdx.x >> 9, n = blockIdx.x & 511;

    for (int i = tid; i < 568; i += 512) {
        float v;
        if      (i < 24)  v = c1w_g[i];
        else if (i < 32)  v = c1b_g[i - 24];
        else if (i < 416) v = c2w_g[i - 32];
        else if (i < 432) v = c2b_g[i - 416];
        else if (i < 560) v = lw_g[i - 432];
        else              v = lb_g[i - 560];
        wall[i] = v;
    }
    const float* wc1 = wall;
    const float* bc1 = wall + 24;
    const float* wc2 = wall + 32;
    const float* bc2 = wall + 416;
    const float* wl  = wall + 432;
    const float* bl  = wall + 560;

    const float* ohb = oh + (size_t)b * NNODE * OHH;
    const float* xb  = xs + (size_t)b * NNODE * CC;
    int off = g_off[b * NNODE + n];
    int m   = g_cnt[b * NNODE + n];
    const int* el = &g_elist[b * EE + off];

    float accoh = ohb[n * OHH + tid];
    float accx  = (tid < CC) ? xb[n * CC + tid] : 0.f;
    for (int i = 0; i < m; i++) {
        int s = el[i];
        accoh += ohb[s * OHH + tid];
        if (tid < CC) accx += xb[s * CC + tid];
    }
    newoh[(size_t)blockIdx.x * OHH + tid] = accoh;
    soh[tid] = accoh;
    if (tid < CC) sx[tid] = accx;
    __syncthreads();

    // bitonic sort ascending (512 elems, 512 threads)
    for (int k = 2; k <= OHH; k <<= 1) {
        for (int j = k >> 1; j > 0; j >>= 1) {
            int ixj = tid ^ j;
            if (ixj > tid) {
                float a = soh[tid], c = soh[ixj];
                bool up = ((tid & k) == 0);
                if ((a > c) == up) { soh[tid] = c; soh[ixj] = a; }
            }
            __syncthreads();
        }
    }

    // symlog in place
    {
        float sv = soh[tid];
        soh[tid] = copysignf(log1pf(fabsf(sv)), sv);
    }
    __syncthreads();

    // conv1: 1 -> 8 channels, k=3, pad 1, relu
    {
        float pm = (tid > 0) ? soh[tid - 1] : 0.f;
        float p0 = soh[tid];
        float pp = (tid < OHH - 1) ? soh[tid + 1] : 0.f;
        #pragma unroll
        for (int c = 0; c < 8; c++)
            hbuf[c][tid + 1] = fmaxf(fmaf(wc1[c*3], pm, fmaf(wc1[c*3+1], p0, fmaf(wc1[c*3+2], pp, bc1[c]))), 0.f);
    }
    if (tid < 8) { hbuf[tid][0] = 0.f; hbuf[tid][OHH + 1] = 0.f; }
    __syncthreads();

    // conv2: 8 -> 16 channels, k=3, pad 1, relu; accumulate mean over t
    float vm[8], v0[8], vp[8];
    #pragma unroll
    for (int ic = 0; ic < 8; ic++) {
        vm[ic] = hbuf[ic][tid];
        v0[ic] = hbuf[ic][tid + 1];
        vp[ic] = hbuf[ic][tid + 2];
    }
    float osum[16];
    #pragma unroll
    for (int oc = 0; oc < 16; oc++) {
        const float* wr = &wc2[oc * 24];
        float acc = bc2[oc];
        #pragma unroll
        for (int ic = 0; ic < 8; ic++) {
            acc = fmaf(wr[ic*3],   vm[ic], acc);
            acc = fmaf(wr[ic*3+1], v0[ic], acc);
            acc = fmaf(wr[ic*3+2], vp[ic], acc);
        }
        osum[oc] = fmaxf(acc, 0.f);
    }

    int lane = tid & 31, wid = tid >> 5;
    #pragma unroll
    for (int oc = 0; oc < 16; oc++) {
        float v = osum[oc];
        for (int s2 = 16; s2 > 0; s2 >>= 1) v += __shfl_down_sync(0xffffffffu, v, s2);
        if (lane == 0) red[wid * 16 + oc] = v;
    }
    __syncthreads();
    if (tid < 16) {
        float s2 = 0.f;
        for (int w = 0; w < 16; w++) s2 += red[w * 16 + tid];
        meansh[tid] = s2 * (1.f / 512.f);
    }
    __syncthreads();
    if (tid < 8) {
        float a = bl[tid];
        #pragma unroll
        for (int oc = 0; oc < 16; oc++) a = fmaf(meansh[oc], wl[oc * 8 + tid], a);
        pohsh[tid] = a;
    }
    __syncthreads();

    float* xrow = &g_xcat[(size_t)blockIdx.x * 136];
    if (tid < CC) xrow[tid] = sx[tid];
    if (tid < 8)  xrow[128 + tid] = pohsh[tid];
}

// ---------------- GEMM1 (8192x136 @ 136x128) + masked BN stats ----------------
#define SM1_FLOATS (136*128 + 64*136)
__global__ void __launch_bounds__(256) k_gemm1(
    const float* __restrict__ w1, const float* __restrict__ b1,
    const int* __restrict__ n_nodes)
{
    extern __shared__ float smem[];
    float* ws = smem;             // 136 x 128
    float* xt = smem + 136 * 128; // 64 x 136
    __shared__ float sb1[128];
    __shared__ int nn[16];
    __shared__ float ssum[128], ssq[128];

    int tid = threadIdx.x;
    int row0 = blockIdx.x * 64;
    for (int i = tid; i < 136 * 128; i += 256) ws[i] = w1[i];
    for (int i = tid; i < 64 * 136; i += 256) xt[i] = g_xcat[(size_t)row0 * 136 + i];
    if (tid < 128) { sb1[tid] = b1[tid]; ssum[tid] = 0.f; ssq[tid] = 0.f; }
    if (tid < 16) nn[tid] = n_nodes[tid];
    __syncthreads();

    int cx = tid & 31, ry = tid >> 5;
    float acc[8][4];
    #pragma unroll
    for (int r = 0; r < 8; r++)
        #pragma unroll
        for (int c = 0; c < 4; c++) acc[r][c] = 0.f;

    for (int k = 0; k < 136; k++) {
        float4 w4 = reinterpret_cast<const float4*>(ws + k * 128)[cx];
        #pragma unroll
        for (int r = 0; r < 8; r++) {
            float xv = xt[(ry * 8 + r) * 136 + k];
            acc[r][0] = fmaf(xv, w4.x, acc[r][0]);
            acc[r][1] = fmaf(xv, w4.y, acc[r][1]);
            acc[r][2] = fmaf(xv, w4.z, acc[r][2]);
            acc[r][3] = fmaf(xv, w4.w, acc[r][3]);
        }
    }

    float ps[4] = {0, 0, 0, 0}, pq[4] = {0, 0, 0, 0};
    #pragma unroll
    for (int r = 0; r < 8; r++) {
        int row = row0 + ry * 8 + r;
        bool msk = (row & 511) < nn[row >> 9];
        float4 v4;
        v4.x = acc[r][0] + sb1[cx * 4 + 0];
        v4.y = acc[r][1] + sb1[cx * 4 + 1];
        v4.z = acc[r][2] + sb1[cx * 4 + 2];
        v4.w = acc[r][3] + sb1[cx * 4 + 3];
        *reinterpret_cast<float4*>(&g_h1[(size_t)row * 128 + cx * 4]) = v4;
        if (msk) {
            ps[0] += v4.x; pq[0] += v4.x * v4.x;
            ps[1] += v4.y; pq[1] += v4.y * v4.y;
            ps[2] += v4.z; pq[2] += v4.z * v4.z;
            ps[3] += v4.w; pq[3] += v4.w * v4.w;
        }
    }
    #pragma unroll
    for (int c = 0; c < 4; c++) {
        atomicAdd(&ssum[cx * 4 + c], ps[c]);
        atomicAdd(&ssq[cx * 4 + c], pq[c]);
    }
    __syncthreads();
    if (tid < 128) {
        atomicAdd(&g_sum[tid], ssum[tid]);
        atomicAdd(&g_sq[tid], ssq[tid]);
    }
}

// ---------------- finalize BN affine ----------------
__global__ void k_finalize(const int* __restrict__ n_nodes,
                           const float* __restrict__ bng, const float* __restrict__ bnb)
{
    __shared__ float cntf;
    int tid = threadIdx.x;
    if (tid == 0) {
        int s = 0;
        for (int b2 = 0; b2 < 16; b2++) s += n_nodes[b2];
        cntf = fmaxf((float)s, 1.f);
    }
    __syncthreads();
    float mean = g_sum[tid] / cntf;
    float var  = g_sq[tid] / cntf - mean * mean;
    float a = rsqrtf(var + 1e-5f) * bng[tid];
    g_a[tid] = a;
    g_c[tid] = bnb[tid] - mean * a;
}

// ---------------- GEMM2 (normalize+relu fused on load, mask on store) ----------------
#define SM2_FLOATS (128*128 + 64*128)
__global__ void __launch_bounds__(256) k_gemm2(
    const float* __restrict__ w2, const float* __restrict__ b2,
    const int* __restrict__ n_nodes, float* __restrict__ outp)
{
    extern __shared__ float smem[];
    float* ws = smem;             // 128 x 128
    float* xt = smem + 128 * 128; // 64 x 128
    __shared__ float sb2[128], sa[128], sc[128];
    __shared__ int nn[16];

    int tid = threadIdx.x;
    int row0 = blockIdx.x * 64;
    for (int i = tid; i < 128 * 128; i += 256) ws[i] = w2[i];
    if (tid < 128) { sa[tid] = g_a[tid]; sc[tid] = g_c[tid]; sb2[tid] = b2[tid]; }
    if (tid < 16) nn[tid] = n_nodes[tid];
    __syncthreads();
    for (int i = tid; i < 64 * 128; i += 256) {
        int k = i & 127;
        float v = g_h1[(size_t)row0 * 128 + i];
        xt[i] = fmaxf(fmaf(v, sa[k], sc[k]), 0.f);
    }
    __syncthreads();

    int cx = tid & 31, ry = tid >> 5;
    float acc[8][4];
    #pragma unroll
    for (int r = 0; r < 8; r++)
        #pragma unroll
        for (int c = 0; c < 4; c++) acc[r][c] = 0.f;

    for (int k = 0; k < 128; k++) {
        float4 w4 = reinterpret_cast<const float4*>(ws + k * 128)[cx];
        #pragma unroll
        for (int r = 0; r < 8; r++) {
            float xv = xt[(ry * 8 + r) * 128 + k];
            acc[r][0] = fmaf(xv, w4.x, acc[r][0]);
            acc[r][1] = fmaf(xv, w4.y, acc[r][1]);
            acc[r][2] = fmaf(xv, w4.z, acc[r][2]);
            acc[r][3] = fmaf(xv, w4.w, acc[r][3]);
        }
    }
    #pragma unroll
    for (int r = 0; r < 8; r++) {
        int row = row0 + ry * 8 + r;
        bool msk = (row & 511) < nn[row >> 9];
        float4 v4;
        if (msk) {
            v4.x = acc[r][0] + sb2[cx * 4 + 0];
            v4.y = acc[r][1] + sb2[cx * 4 + 1];
            v4.z = acc[r][2] + sb2[cx * 4 + 2];
            v4.w = acc[r][3] + sb2[cx * 4 + 3];
        } else {
            v4.x = 0.f; v4.y = 0.f; v4.z = 0.f; v4.w = 0.f;
        }
        *reinterpret_cast<float4*>(&outp[(size_t)row * 128 + cx * 4]) = v4;
    }
}

// ---------------- launcher ----------------
extern "C" void kernel_launch(void* const* d_in, const int* in_sizes, int n_in,
                              void* d_out, int out_size)
{
    const float* xs      = (const float*)d_in[0];
    const float* oh      = (const float*)d_in[1];
    const int*   adjs    = (const int*)d_in[2];
    const int*   n_nodes = (const int*)d_in[3];
    int w = (n_in >= 17) ? 5 : 4;   // skip dim_size scalar if present
    const float* c1w = (const float*)d_in[w + 0];
    const float* c1b = (const float*)d_in[w + 1];
    const float* c2w = (const float*)d_in[w + 2];
    const float* c2b = (const float*)d_in[w + 3];
    const float* lw  = (const float*)d_in[w + 4];
    const float* lb  = (const float*)d_in[w + 5];
    const float* w1  = (const float*)d_in[w + 6];
    const float* b1  = (const float*)d_in[w + 7];
    const float* bng = (const float*)d_in[w + 8];
    const float* bnb = (const float*)d_in[w + 9];
    const float* w2  = (const float*)d_in[w + 10];
    const float* b2  = (const float*)d_in[w + 11];

    float* outp  = (float*)d_out;
    float* newoh = outp + (size_t)ROWS * 128;

    cudaFuncSetAttribute(k_gemm1, cudaFuncAttributeMaxDynamicSharedMemorySize, SM1_FLOATS * 4);
    cudaFuncSetAttribute(k_gemm2, cudaFuncAttributeMaxDynamicSharedMemorySize, SM2_FLOATS * 4);

    k_zero <<<32, 256>>>();
    k_count<<<512, 256>>>(adjs);
    k_scan <<<16, 512>>>();
    k_fill <<<512, 256>>>(adjs);
    k_fused<<<ROWS, 512>>>(xs, oh, c1w, c1b, c2w, c2b, lw, lb, newoh);
    k_gemm1<<<128, 256, SM1_FLOATS * 4>>>(w1, b1, n_nodes);
    k_finalize<<<1, 128>>>(n_nodes, bng, bnb);
    k_gemm2<<<128, 256, SM2_FLOATS * 4>>>(w2, b2, n_nodes, outp);
}